// round 15
// baseline (speedup 1.0000x reference)
#include <cuda_runtime.h>
#include <math.h>

#define Bn   16
#define Tn   750
#define Fd   4096
#define Cd   20
#define KS   93
#define NROW (Bn*Tn)          // 12000

// ---- output layout (float elements) ----
#define OFF_SACT 0
#define OFF_SBKG 320
#define OFF_FACT 640
#define OFF_FBKG 6095488
#define OFF_FEAT 12190336
#define OFF_CSM  61342336

// ---- device scratch ----
__device__ float g_cas[NROW*Cd];
__device__ float g_mag[NROW];
__device__ int   g_idx_act[Bn*KS];
__device__ int   g_idx_bkg[Bn*KS];
__device__ float g_sact[Bn*Cd];

// ---- cp.async helpers ----
__device__ __forceinline__ unsigned smem_u32(const void* p) {
    return (unsigned)__cvta_generic_to_shared(p);
}
__device__ __forceinline__ void cp16(unsigned dst, const void* src) {
    asm volatile("cp.async.cg.shared.global [%0], [%1], 16;"
                 :: "r"(dst), "l"(src) : "memory");
}
#define CP_COMMIT() asm volatile("cp.async.commit_group;" ::: "memory")
#define CP_WAIT(n)  asm volatile("cp.async.wait_group %0;" :: "n"(n) : "memory")

// ============================================================================
// K1: fused per-row pass, direct-LDG x/mask (no staging ring; one barrier
// per W chunk). 600 blocks x 320 threads, 20 rows/block, 2 blk/SM.
// 10 warps = 5 row-groups x 2 class-warps; per warp 4 rows x 10 classes,
// scalar fp32 acc. Both class-warps LDG identical x/m addresses -> L1
// pending-hit merge keeps DRAM traffic unchanged.
// W: cp.async double-buffer [2][20][64] f4; 16 chunks x 2 subs = 32 subs
// covering all 1024 f4 of the K dimension.  smem: W 40960 + cass 1600.
// ============================================================================
#define SM_OFF_W    0
#define SM_OFF_CASS 40960
#define SM_TOTAL    42560

__global__ __launch_bounds__(320, 2) void k1_main(
    const float4* __restrict__ xg, const float4* __restrict__ Wg,
    const float4* __restrict__ mg, float4* __restrict__ featg,
    float* __restrict__ cas_sm)
{
    extern __shared__ char sm[];
    float4* smw  = (float4*)(sm + SM_OFF_W);     // [2][20][64]
    float*  cass = (float*)(sm + SM_OFF_CASS);   // [20][Cd]

    const int tid  = threadIdx.x;
    const int lane = tid & 31;
    const int wrp  = tid >> 5;           // 0..9
    const int rg   = wrp >> 1;           // row-group 0..4 -> rows rg*4..rg*4+3
    const int cw   = wrp & 1;            // class-warp -> classes cw*10..+9
    const int cbase = cw * 10;
    const int row0 = blockIdx.x * 20;
    const int rbase = row0 + rg * 4;     // this warp's 4 rows

    const float4* xr0 = xg + (size_t)rbase * 1024 + lane;
    const float4* mr0 = mg + (size_t)rbase * 1024 + lane;
    float4*       fr0 = featg + (size_t)rbase * 1024 + lane;
    const unsigned wsm = smem_u32(smw);

    float acc[10][4];
    #pragma unroll
    for (int c = 0; c < 10; c++)
        #pragma unroll
        for (int r = 0; r < 4; r++) acc[c][r] = 0.f;
    float ssq[4] = {0.f, 0.f, 0.f, 0.f};

    // ---- prologue: W chunk 0 (f4 [0,64)) -> buf 0 ----
    #pragma unroll
    for (int i = 0; i < 4; i++) {
        int k = tid + i * 320;                    // 0..1279
        int c = k >> 6, p = k & 63;
        cp16(wsm + (unsigned)k * 16u, Wg + c * 1024 + p);
    }
    CP_COMMIT();

    #define COMPUTE_SUB(s, wbuf)                                                \
    {                                                                           \
        const int fi = (s) * 32;                                                \
        float4 xm[4];                                                           \
        /* row pair 0,1 */                                                      \
        {                                                                       \
            float4 xv0 = __ldg(xr0 + fi);                                       \
            float4 mv0 = __ldg(mr0 + fi);                                       \
            float4 xv1 = __ldg(xr0 + 1024 + fi);                                \
            float4 mv1 = __ldg(mr0 + 1024 + fi);                                \
            if (cw == 0) {                                                      \
                __stcs(fr0 + fi, xv0);                                          \
                __stcs(fr0 + 1024 + fi, xv1);                                   \
                ssq[0] += xv0.x*xv0.x + xv0.y*xv0.y + xv0.z*xv0.z + xv0.w*xv0.w;\
                ssq[1] += xv1.x*xv1.x + xv1.y*xv1.y + xv1.z*xv1.z + xv1.w*xv1.w;\
            }                                                                   \
            xm[0].x = xv0.x*mv0.x; xm[0].y = xv0.y*mv0.y;                       \
            xm[0].z = xv0.z*mv0.z; xm[0].w = xv0.w*mv0.w;                       \
            xm[1].x = xv1.x*mv1.x; xm[1].y = xv1.y*mv1.y;                       \
            xm[1].z = xv1.z*mv1.z; xm[1].w = xv1.w*mv1.w;                       \
        }                                                                       \
        /* row pair 2,3 */                                                      \
        {                                                                       \
            float4 xv2 = __ldg(xr0 + 2048 + fi);                                \
            float4 mv2 = __ldg(mr0 + 2048 + fi);                                \
            float4 xv3 = __ldg(xr0 + 3072 + fi);                                \
            float4 mv3 = __ldg(mr0 + 3072 + fi);                                \
            if (cw == 0) {                                                      \
                __stcs(fr0 + 2048 + fi, xv2);                                   \
                __stcs(fr0 + 3072 + fi, xv3);                                   \
                ssq[2] += xv2.x*xv2.x + xv2.y*xv2.y + xv2.z*xv2.z + xv2.w*xv2.w;\
                ssq[3] += xv3.x*xv3.x + xv3.y*xv3.y + xv3.z*xv3.z + xv3.w*xv3.w;\
            }                                                                   \
            xm[2].x = xv2.x*mv2.x; xm[2].y = xv2.y*mv2.y;                       \
            xm[2].z = xv2.z*mv2.z; xm[2].w = xv2.w*mv2.w;                       \
            xm[3].x = xv3.x*mv3.x; xm[3].y = xv3.y*mv3.y;                       \
            xm[3].z = xv3.z*mv3.z; xm[3].w = xv3.w*mv3.w;                       \
        }                                                                       \
        const int wbase = (wbuf) * 1280 + ((s) & 1) * 32;                       \
        _Pragma("unroll")                                                       \
        for (int c = 0; c < 10; c++) {                                          \
            float4 wv = smw[wbase + (cbase + c) * 64 + lane];                   \
            _Pragma("unroll")                                                   \
            for (int r = 0; r < 4; r++) {                                       \
                float a = acc[c][r];                                            \
                a = fmaf(wv.x, xm[r].x, a);                                     \
                a = fmaf(wv.y, xm[r].y, a);                                     \
                a = fmaf(wv.z, xm[r].z, a);                                     \
                a = fmaf(wv.w, xm[r].w, a);                                     \
                acc[c][r] = a;                                                  \
            }                                                                   \
        }                                                                       \
    }

    // ---- main loop: 16 W chunks x 2 subs = all 32 sub-chunks ----
    for (int ch = 0; ch < 16; ch++) {
        CP_WAIT(0);
        __syncthreads();
        if (ch < 15) {   // prefetch next W chunk into the other buffer
            const float4* Wsrc = Wg + (ch + 1) * 64;
            unsigned dst = wsm + (unsigned)(((ch + 1) & 1) * 1280) * 16u;
            #pragma unroll
            for (int i = 0; i < 4; i++) {
                int k = tid + i * 320;
                int c = k >> 6, p = k & 63;
                cp16(dst + (unsigned)k * 16u, Wsrc + c * 1024 + p);
            }
            CP_COMMIT();
        }
        const int buf = ch & 1;
        COMPUTE_SUB(2 * ch,     buf);
        COMPUTE_SUB(2 * ch + 1, buf);
    }

    // ---- warp-local cas reduction (4 rows x 10 classes per warp) ----
    #pragma unroll
    for (int c = 0; c < 10; c++) {
        #pragma unroll
        for (int r = 0; r < 4; r++) {
            float s2 = acc[c][r];
            s2 += __shfl_down_sync(0xffffffffu, s2, 16);
            s2 += __shfl_down_sync(0xffffffffu, s2, 8);
            s2 += __shfl_down_sync(0xffffffffu, s2, 4);
            s2 += __shfl_down_sync(0xffffffffu, s2, 2);
            s2 += __shfl_down_sync(0xffffffffu, s2, 1);
            if (lane == 0) {
                int cc = cbase + c;
                int lrow = rg * 4 + r;
                cass[lrow * Cd + cc] = s2;
                g_cas[(row0 + lrow) * Cd + cc] = s2;
            }
        }
    }
    // ---- mag: cw==0 warps reduce their 4 rows (fp64 cross-lane) ----
    if (cw == 0) {
        #pragma unroll
        for (int r = 0; r < 4; r++) {
            double d = (double)ssq[r];
            d += __shfl_down_sync(0xffffffffu, d, 16);
            d += __shfl_down_sync(0xffffffffu, d, 8);
            d += __shfl_down_sync(0xffffffffu, d, 4);
            d += __shfl_down_sync(0xffffffffu, d, 2);
            d += __shfl_down_sync(0xffffffffu, d, 1);
            if (lane == 0) g_mag[row0 + rg * 4 + r] = (float)sqrt(d);
        }
    }
    __syncthreads();

    // ---- cas softmax over classes, one thread per row ----
    if (tid < 20) {
        int row = row0 + tid;
        float m = -1e30f;
        #pragma unroll
        for (int c = 0; c < Cd; c++) m = fmaxf(m, cass[tid * Cd + c]);
        float e[Cd]; float s = 0.f;
        #pragma unroll
        for (int c = 0; c < Cd; c++) { e[c] = expf(cass[tid * Cd + c] - m); s += e[c]; }
        float inv = 1.f / s;
        #pragma unroll
        for (int c = 0; c < Cd; c++) cas_sm[row * Cd + c] = e[c] * inv;
    }
}

// ============================================================================
// K23: merged top-k kernels. grid 88 x 256 threads.
//  blocks [0,48): K2 — per-batch ordered top-93 (rank counting, 250 cand/blk)
//  blocks [48,88): K3 — warp-per-(b,c) radix select for score_act sums
// ============================================================================
__global__ void k23(const float* __restrict__ sel)
{
    __shared__ float sh[12000];
    __shared__ float wmax[8];
    const int tid = threadIdx.x;

    if (blockIdx.x < 48) {
        const int b = blockIdx.x / 3, chunk = blockIdx.x % 3;
        float* md  = sh;
        float* mrd = sh + Tn;

        float lmax = -1e30f;
        for (int i = tid; i < Tn; i += 256) {
            float m = g_mag[b * Tn + i];
            float s = sel[b * Tn + i];
            md[i] = m; mrd[i] = s;
            lmax = fmaxf(lmax, m);
        }
        for (int o = 16; o > 0; o >>= 1)
            lmax = fmaxf(lmax, __shfl_down_sync(0xffffffffu, lmax, o));
        if ((tid & 31) == 0) wmax[tid >> 5] = lmax;
        __syncthreads();
        float maxm = wmax[0];
        #pragma unroll
        for (int w = 1; w < 8; w++) maxm = fmaxf(maxm, wmax[w]);
        for (int i = tid; i < Tn; i += 256) {
            float m = md[i], s = mrd[i];
            md[i]  = m * s;
            mrd[i] = (maxm - m) * s;
        }
        __syncthreads();

        const int i = chunk * 250 + tid;
        if (tid < 250) {
            float v1 = md[i], v2 = mrd[i];
            int r1 = 0, r2 = 0;
            #pragma unroll 5
            for (int j = 0; j < Tn; j++) {
                float u1 = md[j];
                r1 += (int)(u1 > v1) + (int)((u1 == v1) & (j < i));
                float u2 = mrd[j];
                r2 += (int)(u2 > v2) + (int)((u2 == v2) & (j < i));
            }
            if (r1 < KS) g_idx_act[b * KS + r1] = i;
            if (r2 < KS) g_idx_bkg[b * KS + r2] = i;
        }
    } else {
        const int w = tid >> 5, lane = tid & 31;
        const int pair = (blockIdx.x - 48) * 8 + w;   // 0..319
        const int b = pair / Cd, c = pair % Cd;
        unsigned* key = (unsigned*)(sh + w * 1500);
        float*    col = sh + w * 1500 + Tn;

        for (int i = lane; i < Tn; i += 32) {
            float v = g_cas[(b * Tn + i) * Cd + c];
            col[i] = v;
            unsigned u = __float_as_uint(v);
            key[i] = (u & 0x80000000u) ? ~u : (u | 0x80000000u);
        }
        __syncwarp();

        unsigned prefix = 0u;
        for (int bit = 31; bit >= 0; --bit) {
            unsigned cand = prefix | (1u << bit);
            int cnt = 0;
            for (int i = lane; i < Tn; i += 32) cnt += (int)(key[i] >= cand);
            cnt = (int)__reduce_add_sync(0xffffffffu, (unsigned)cnt);
            if (cnt >= KS) prefix = cand;
        }
        float thr;
        { unsigned u = prefix; u = (u & 0x80000000u) ? (u & 0x7fffffffu) : ~u;
          thr = __uint_as_float(u); }

        int cg = 0; float s = 0.f;
        for (int i = lane; i < Tn; i += 32)
            if (key[i] > prefix) { cg++; s += col[i]; }
        cg = (int)__reduce_add_sync(0xffffffffu, (unsigned)cg);
        for (int o = 16; o > 0; o >>= 1) s += __shfl_down_sync(0xffffffffu, s, o);
        if (lane == 0)
            g_sact[b * Cd + c] = (s + (float)(KS - cg) * thr) * (1.f / (float)KS);
    }
}

// ============================================================================
// K45: merged tail. grid 2992 x 256 threads.
// ============================================================================
__global__ void k45(const float4* __restrict__ x4, float* __restrict__ out)
{
    __shared__ float red[12 * Cd];
    __shared__ float sb[Cd], sa[Cd], eb[Cd], ea[Cd];
    const int tid = threadIdx.x;

    if (blockIdx.x < 2976) {
        int idx = blockIdx.x;
        int z = (idx >= 1488) ? 1 : 0;
        idx -= z * 1488;
        const int b = idx / KS, k = idx % KS;
        const int* I = z ? g_idx_bkg : g_idx_act;
        const int t = I[b * KS + k];
        const float4* s = x4 + (long)(b * Tn + t) * 1024;
        float4* d = (float4*)out + (z ? (OFF_FBKG / 4) : (OFF_FACT / 4))
                    + (long)(b * KS + k) * 1024;
        for (int i = tid; i < 1024; i += 256) __stcs(d + i, __ldg(s + i));
    } else {
        const int b = blockIdx.x - 2976;
        float* score_act = out + OFF_SACT;
        float* score_bkg = out + OFF_SBKG;

        if (tid < 240) {
            int c = tid % Cd, p = tid / Cd;
            float s = 0.f;
            for (int k = p; k < KS; k += 12) {
                int t = g_idx_bkg[b * KS + k];
                s += g_cas[(b * Tn + t) * Cd + c];
            }
            red[p * Cd + c] = s;
        }
        __syncthreads();
        if (tid < Cd) {
            float s = 0.f;
            #pragma unroll
            for (int p = 0; p < 12; p++) s += red[p * Cd + tid];
            sb[tid] = s * (1.f / (float)KS);
            sa[tid] = g_sact[b * Cd + tid];
        }
        __syncthreads();
        if (tid < Cd) {
            float mb = -1e30f, ma = -1e30f;
            #pragma unroll
            for (int j = 0; j < Cd; j++) { mb = fmaxf(mb, sb[j]); ma = fmaxf(ma, sa[j]); }
            eb[tid] = expf(sb[tid] - mb);
            ea[tid] = expf(sa[tid] - ma);
        }
        __syncthreads();
        if (tid < Cd) {
            float Sb = 0.f, Sa = 0.f;
            #pragma unroll
            for (int j = 0; j < Cd; j++) { Sb += eb[j]; Sa += ea[j]; }
            score_bkg[b * Cd + tid] = eb[tid] / Sb;
            score_act[b * Cd + tid] = ea[tid] / Sa;
        }
    }
}

// ============================================================================
extern "C" void kernel_launch(void* const* d_in, const int* in_sizes, int n_in,
                              void* d_out, int out_size)
{
    const float* x    = (const float*)d_in[0];
    const float* W    = (const float*)d_in[1];
    const float* mask = (const float*)d_in[2];
    const float* sel  = (const float*)d_in[3];
    float* out = (float*)d_out;

    cudaFuncSetAttribute(k1_main, cudaFuncAttributeMaxDynamicSharedMemorySize, SM_TOTAL);

    k1_main<<<NROW / 20, 320, SM_TOTAL>>>(
        (const float4*)x, (const float4*)W, (const float4*)mask,
        (float4*)(out + OFF_FEAT), out + OFF_CSM);
    k23<<<88, 256>>>(sel);
    k45<<<2992, 256>>>((const float4*)x, out);
}